// round 8
// baseline (speedup 1.0000x reference)
#include <cuda_runtime.h>
#include <math.h>

#define D_DIM 3072
#define C_DIM 10
#define B_DIM 4096
#define BLOCKS 148
#define WARPSN 12
#define BLOCK 384
#define MAXR 28          // max rows per block (blocks 0..99: 28, 100..147: 27)
#define NG 14            // row groups of 2 (28/2) — same for 27 (last clamped)

#define EPS_REG 0.1f
#define NUM_STAB 1e-6f

typedef unsigned long long u64;

__device__ float g_partials[BLOCKS];
__device__ unsigned int g_count = 0;

// ---- packed fp32x2 helpers ----
__device__ __forceinline__ u64 ffma2(u64 a, u64 b, u64 c) {
    u64 d; asm("fma.rn.f32x2 %0, %1, %2, %3;" : "=l"(d) : "l"(a), "l"(b), "l"(c));
    return d;
}
__device__ __forceinline__ u64 add2(u64 a, u64 b) {
    u64 d; asm("add.rn.f32x2 %0, %1, %2;" : "=l"(d) : "l"(a), "l"(b));
    return d;
}
__device__ __forceinline__ u64 pk2(float a, float b) {
    u64 r; asm("mov.b64 %0, {%1, %2};" : "=l"(r) : "f"(a), "f"(b));
    return r;
}
__device__ __forceinline__ u64 shfl64(u64 v, int m) {
    unsigned lo, hi;
    asm("mov.b64 {%0, %1}, %2;" : "=r"(lo), "=r"(hi) : "l"(v));
    lo = __shfl_xor_sync(0xffffffffu, lo, m);
    hi = __shfl_xor_sync(0xffffffffu, hi, m);
    u64 r; asm("mov.b64 %0, {%1, %2};" : "=l"(r) : "r"(lo), "r"(hi));
    return r;
}
__device__ __forceinline__ void unpk(u64 v, float& lo, float& hi) {
    asm("mov.b64 {%0, %1}, %2;" : "=f"(lo), "=f"(hi) : "l"(v));
}

// ---- L2-scoped sync helpers (no threadfence -> no L1 flush) ----
__device__ __forceinline__ void st_cg(float* p, float v) {
    asm volatile("st.cg.f32 [%0], %1;" :: "l"(p), "f"(v) : "memory");
}
__device__ __forceinline__ float ld_cg(const float* p) {
    float v; asm volatile("ld.cg.f32 %0, [%1];" : "=f"(v) : "l"(p) : "memory");
    return v;
}
__device__ __forceinline__ unsigned atom_add_acqrel(unsigned* p, unsigned v) {
    unsigned old;
    asm volatile("atom.acq_rel.gpu.add.u32 %0, [%1], %2;"
                 : "=r"(old) : "l"(p), "r"(v) : "memory");
    return old;
}

// upper-triangle index into M (a<=b): a*10 - a(a+1)/2 + b
__device__ __forceinline__ float Mget(const float* sM55, int a, int b) {
    int i = (a < b) ? a : b;
    int j = (a < b) ? b : a;
    return sM55[i * 10 - (i * (i + 1)) / 2 + j];
}

// process 2 rows: 80 FFMA2 against register-resident W, 3-round packed
// butterfly, 4 partial lanes store to smem
__device__ __forceinline__ void process2(
    int lr0, float4 x0a, float4 x0b, float4 x1a, float4 x1b,
    const u64 (&wp)[8][5], u64* sZq, int w, int lane)
{
    u64 xx0[8], xx1[8];
    xx0[0]=pk2(x0a.x,x0a.x); xx0[1]=pk2(x0a.y,x0a.y);
    xx0[2]=pk2(x0a.z,x0a.z); xx0[3]=pk2(x0a.w,x0a.w);
    xx0[4]=pk2(x0b.x,x0b.x); xx0[5]=pk2(x0b.y,x0b.y);
    xx0[6]=pk2(x0b.z,x0b.z); xx0[7]=pk2(x0b.w,x0b.w);
    xx1[0]=pk2(x1a.x,x1a.x); xx1[1]=pk2(x1a.y,x1a.y);
    xx1[2]=pk2(x1a.z,x1a.z); xx1[3]=pk2(x1a.w,x1a.w);
    xx1[4]=pk2(x1b.x,x1b.x); xx1[5]=pk2(x1b.y,x1b.y);
    xx1[6]=pk2(x1b.z,x1b.z); xx1[7]=pk2(x1b.w,x1b.w);

    u64 pz0[5], pz1[5];
    #pragma unroll
    for (int jp = 0; jp < 5; jp++) { pz0[jp] = 0ULL; pz1[jp] = 0ULL; }
    #pragma unroll
    for (int d = 0; d < 8; d++) {
        #pragma unroll
        for (int jp = 0; jp < 5; jp++) {
            pz0[jp] = ffma2(xx0[d], wp[d][jp], pz0[jp]);
            pz1[jp] = ffma2(xx1[d], wp[d][jp], pz1[jp]);
        }
    }
    #pragma unroll
    for (int jp = 0; jp < 5; jp++) {
        u64 v0 = pz0[jp], v1 = pz1[jp];
        v0 = add2(v0, shfl64(v0, 16)); v1 = add2(v1, shfl64(v1, 16));
        v0 = add2(v0, shfl64(v0, 8));  v1 = add2(v1, shfl64(v1, 8));
        v0 = add2(v0, shfl64(v0, 4));  v1 = add2(v1, shfl64(v1, 4));
        pz0[jp] = v0; pz1[jp] = v1;
    }
    if (lane < 4) {   // lane q holds sum over lanes == q (mod 4)
        u64* b0 = sZq + (size_t)((lr0 * WARPSN + w) * 4 + lane) * 5;
        u64* b1 = sZq + (size_t)(((lr0 + 1) * WARPSN + w) * 4 + lane) * 5;
        #pragma unroll
        for (int jp = 0; jp < 5; jp++) { b0[jp] = pz0[jp]; b1[jp] = pz1[jp]; }
    }
}

// smem float layout:
//   [0, 13440)        sZq  : 6720 u64 = [28 rows][12 w][4 q][5 jp]
//   [13440, 16080)    sMq  : [12 w][4 q][55]
//   [16080, 16360)    sZr  : [28][10] combined logits
//   [16360, 16415)    sM55 : upper-tri M
extern __shared__ float smem[];

__global__ __launch_bounds__(BLOCK, 1)
void jac_kernel(const float* __restrict__ data,
                const float* __restrict__ W,
                float* __restrict__ out) {
    u64*   sZq  = (u64*)smem;
    float* sZf  = smem;            // float view of sZq
    float* sMq  = smem + 13440;
    float* sZr  = smem + 16080;
    float* sM55 = smem + 16360;
    __shared__ float sWsum[WARPSN];
    __shared__ bool  sIsLast;

    const int tid  = threadIdx.x;
    const int w    = tid >> 5;
    const int lane = tid & 31;
    const int b    = blockIdx.x;
    const int nrb     = (b < 100) ? 28 : 27;
    const int rowbase = (b < 100) ? 28 * b : 2800 + 27 * (b - 100);

    // ---- load this lane's W slice into registers (packed j-pairs) ----
    u64 wp[8][5];
    {
        const float2* wptr = (const float2*)(W + (size_t)(w * 256 + lane * 8) * C_DIM);
        #pragma unroll
        for (int d = 0; d < 8; d++)
            #pragma unroll
            for (int jp = 0; jp < 5; jp++) {
                float2 t = wptr[d * 5 + jp];
                wp[d][jp] = pk2(t.x, t.y);
            }
    }

    const float* xbase = data + (size_t)rowbase * D_DIM + w * 256 + lane * 8;

    // ---- mainloop: 14 groups of 2 rows, double-buffered x loads ----
    float4 A0, A1, A2, A3, B0, B1, B2, B3;
    {
        const float4* p0 = (const float4*)(xbase);
        const float4* p1 = (const float4*)(xbase + D_DIM);
        A0 = p0[0]; A1 = p0[1]; A2 = p1[0]; A3 = p1[1];
    }
    #pragma unroll
    for (int g = 0; g < NG; g += 2) {
        {   // prefetch group g+1 (always exists: NG even)
            int e0 = min(2 * (g + 1),     nrb - 1);
            int e1 = min(2 * (g + 1) + 1, nrb - 1);
            const float4* p0 = (const float4*)(xbase + (size_t)e0 * D_DIM);
            const float4* p1 = (const float4*)(xbase + (size_t)e1 * D_DIM);
            B0 = p0[0]; B1 = p0[1]; B2 = p1[0]; B3 = p1[1];
        }
        process2(2 * g, A0, A1, A2, A3, wp, sZq, w, lane);
        if (g + 2 < NG) {   // prefetch group g+2
            int e0 = min(2 * (g + 2),     nrb - 1);
            int e1 = min(2 * (g + 2) + 1, nrb - 1);
            const float4* p0 = (const float4*)(xbase + (size_t)e0 * D_DIM);
            const float4* p1 = (const float4*)(xbase + (size_t)e1 * D_DIM);
            A0 = p0[0]; A1 = p0[1]; A2 = p1[0]; A3 = p1[1];
        }
        process2(2 * (g + 1), B0, B1, B2, B3, wp, sZq, w, lane);
    }

    // ---- M = W^T W partials from register-resident W ----
    {
        float macc[55];
        #pragma unroll
        for (int k = 0; k < 55; k++) macc[k] = 0.f;
        #pragma unroll
        for (int d = 0; d < 8; d++) {
            float wv[10];
            #pragma unroll
            for (int jp = 0; jp < 5; jp++) unpk(wp[d][jp], wv[2 * jp], wv[2 * jp + 1]);
            int idx = 0;
            #pragma unroll
            for (int a = 0; a < 10; a++)
                #pragma unroll
                for (int bb = a; bb < 10; bb++) {
                    macc[idx] = fmaf(wv[a], wv[bb], macc[idx]);
                    idx++;
                }
        }
        #pragma unroll
        for (int k = 0; k < 55; k++) {
            float v = macc[k];
            v += __shfl_xor_sync(0xffffffffu, v, 16);
            v += __shfl_xor_sync(0xffffffffu, v, 8);
            v += __shfl_xor_sync(0xffffffffu, v, 4);
            macc[k] = v;
        }
        if (lane < 4) {
            float* mb = sMq + (w * 4 + lane) * 55;
            #pragma unroll
            for (int k = 0; k < 55; k++) mb[k] = macc[k];
        }
    }
    __syncthreads();

    // ---- phase 1: combine partials (fixed order -> deterministic) ----
    if (tid < MAXR * C_DIM) {                       // 280 z-tasks
        const int row = tid / C_DIM, j = tid - row * C_DIM;
        float s = 0.f;
        #pragma unroll
        for (int w2 = 0; w2 < WARPSN; w2++)
            #pragma unroll
            for (int q = 0; q < 4; q++)
                s += sZf[(size_t)((row * WARPSN + w2) * 4 + q) * 10 + j];
        sZr[tid] = s;
    } else if (tid < MAXR * C_DIM + 55) {           // 55 M-tasks
        const int t = tid - MAXR * C_DIM;
        float s = 0.f;
        #pragma unroll
        for (int w2 = 0; w2 < WARPSN; w2++)
            #pragma unroll
            for (int q = 0; q < 4; q++)
                s += sMq[(w2 * 4 + q) * 55 + t];
        sM55[t] = s;
    }
    __syncthreads();

    // ---- analytic epilogue: thread t handles row rowbase+t ----
    float reg = 0.f;
    if (tid < nrb) {
        const float ALPHA = 1.0f - (float)C_DIM * NUM_STAB;
        float z[C_DIM];
        #pragma unroll
        for (int j = 0; j < C_DIM; j++) z[j] = sZr[tid * C_DIM + j];

        float zmax = z[0];
        #pragma unroll
        for (int j = 1; j < C_DIM; j++) zmax = fmaxf(zmax, z[j]);

        float e[C_DIM], S = 0.f;
        #pragma unroll
        for (int j = 0; j < C_DIM; j++) { e[j] = expf(z[j] - zmax); S += e[j]; }
        const float invS = 1.f / S;

        float sig[C_DIM], p[C_DIM], s[C_DIM];
        float ssum = 0.f, psum_m = 0.f;
        #pragma unroll
        for (int j = 0; j < C_DIM; j++) {
            sig[j] = e[j] * invS;
            p[j]   = fmaf(ALPHA, sig[j], NUM_STAB);
            s[j]   = sqrtf(p[j]);
            ssum  += s[j];
            if (j < C_DIM - 1) psum_m += p[j];
        }
        const float sL = s[C_DIM - 1];
        const float t  = 1.f / (1.f - sL);

        float arg = ssum * 0.31622776601683794f;   // 1/sqrt(10)
        arg = fminf(1.f, fmaxf(-1.f, arg));
        const float delta = 2.f * acosf(arg);
        const float rho   = (2.f * (1.f - sL) - psum_m) * t;

        // v = M sigma, q = sigma^T M sigma
        float v[C_DIM], q = 0.f;
        #pragma unroll
        for (int k = 0; k < C_DIM; k++) {
            float a = 0.f;
            #pragma unroll
            for (int j = 0; j < C_DIM; j++)
                a = fmaf(Mget(sM55, k, j), sig[j], a);
            v[k] = a;
            q = fmaf(sig[k], a, q);
        }

        // ||J||_F^2 = sum_i g_i^T M g_i,  g_i = a_i e_i + b_i e_L - (a_i+b_i) sigma
        const float gL = ALPHA * sig[C_DIM - 1] / sL;
        float fro = 0.f;
        #pragma unroll
        for (int i = 0; i < C_DIM - 1; i++) {
            float a = t * ALPHA * sig[i] / s[i];
            float bb = s[i] * t * t * gL;
            float c = a + bb;
            fro += a * a * Mget(sM55, i, i)
                 + bb * bb * Mget(sM55, 9, 9)
                 + c * c * q
                 + 2.f * a * bb * Mget(sM55, i, 9)
                 - 2.f * c * (a * v[i] + bb * v[C_DIM - 1]);
        }
        const float jac_norm = sqrtf(fmaxf(fro, 0.f));

        const float xv = jac_norm - delta / (rho * EPS_REG);
        reg = (xv > 0.f) ? xv : (expf(xv) - 1.f);
    }

    // ---- block partial (all epilogue threads are in warp 0) ----
    if (w == 0) {
        #pragma unroll
        for (int off = 16; off; off >>= 1)
            reg += __shfl_xor_sync(0xffffffffu, reg, off);
    }
    __syncthreads();
    if (tid == 0) {
        st_cg(&g_partials[b], reg);
        sIsLast = (atom_add_acqrel(&g_count, 1u) == BLOCKS - 1);
    }
    __syncthreads();

    // ---- last block: fixed-order final reduction ----
    if (sIsLast) {
        float v = (tid < BLOCKS) ? ld_cg(&g_partials[tid]) : 0.f;
        #pragma unroll
        for (int off = 16; off; off >>= 1)
            v += __shfl_xor_sync(0xffffffffu, v, off);
        if (lane == 0) sWsum[w] = v;
        __syncthreads();
        if (tid == 0) {
            float ssum = 0.f;
            #pragma unroll
            for (int k = 0; k < WARPSN; k++) ssum += sWsum[k];
            out[0] = ssum * (1.0f / (float)B_DIM);
            asm volatile("st.cg.u32 [%0], %1;" :: "l"(&g_count), "r"(0u) : "memory");
        }
    }
}

extern "C" void kernel_launch(void* const* d_in, const int* in_sizes, int n_in,
                              void* d_out, int out_size) {
    const float* data = (const float*)d_in[0];   // [4096, 3072] f32
    const float* W    = (const float*)d_in[1];   // [3072, 10]   f32
    float* out        = (float*)d_out;           // scalar f32

    const int smemBytes = 16415 * 4 + 128;       // ~65.8 KB
    cudaFuncSetAttribute(jac_kernel, cudaFuncAttributeMaxDynamicSharedMemorySize,
                         smemBytes);
    jac_kernel<<<BLOCKS, BLOCK, smemBytes>>>(data, W, out);
}

// round 9
// speedup vs baseline: 1.1078x; 1.1078x over previous
#include <cuda_runtime.h>
#include <math.h>

typedef unsigned long long u64;

#define D_DIM 3072
#define C_DIM 10
#define B_DIM 4096
#define QN 4                 // D quarters
#define DQ 768               // D per quarter
#define SETROWS 32
#define NSETS 128            // 4096/32
#define NBLOCKS (NSETS * QN) // 512: block = set*4 + q
#define THREADS 128
#define NIT 6                // 768 / 128
#define RW 8                 // rows per warp (4 warps * 8 = 32 = SETROWS)

#define EPS_REG 0.1f
#define NUM_STAB 1e-6f

// device scratch (no cudaMalloc allowed); zero-init at load, reset each launch
__device__ u64 g_zpart[B_DIM * QN * 5];   // per-row per-quarter packed z partials
__device__ float g_M55[55];
__device__ float g_partials[NSETS];
__device__ unsigned g_setcnt[NSETS];
__device__ unsigned g_Mdone = 0;
__device__ unsigned g_count = 0;

// ---- packed fp32x2 helpers ----
__device__ __forceinline__ u64 ffma2(u64 a, u64 b, u64 c) {
    u64 d; asm("fma.rn.f32x2 %0, %1, %2, %3;" : "=l"(d) : "l"(a), "l"(b), "l"(c));
    return d;
}
__device__ __forceinline__ u64 add2(u64 a, u64 b) {
    u64 d; asm("add.rn.f32x2 %0, %1, %2;" : "=l"(d) : "l"(a), "l"(b));
    return d;
}
__device__ __forceinline__ u64 pk2(float a, float b) {
    u64 r; asm("mov.b64 %0, {%1, %2};" : "=l"(r) : "f"(a), "f"(b));
    return r;
}
__device__ __forceinline__ void unpk(u64 v, float& lo, float& hi) {
    asm("mov.b64 {%0, %1}, %2;" : "=f"(lo), "=f"(hi) : "l"(v));
}
__device__ __forceinline__ u64 shfl64(u64 v, int m) {
    unsigned lo, hi;
    asm("mov.b64 {%0, %1}, %2;" : "=r"(lo), "=r"(hi) : "l"(v));
    lo = __shfl_xor_sync(0xffffffffu, lo, m);
    hi = __shfl_xor_sync(0xffffffffu, hi, m);
    u64 r; asm("mov.b64 %0, {%1, %2};" : "=l"(r) : "r"(lo), "r"(hi));
    return r;
}

// ---- L2-scoped helpers (no threadfence -> no L1 flush) ----
__device__ __forceinline__ void st_cg_u64(u64* p, u64 v) {
    asm volatile("st.cg.u64 [%0], %1;" :: "l"(p), "l"(v) : "memory");
}
__device__ __forceinline__ u64 ld_cg_u64(const u64* p) {
    u64 v; asm volatile("ld.cg.u64 %0, [%1];" : "=l"(v) : "l"(p) : "memory");
    return v;
}
__device__ __forceinline__ void st_cg_f(float* p, float v) {
    asm volatile("st.cg.f32 [%0], %1;" :: "l"(p), "f"(v) : "memory");
}
__device__ __forceinline__ float ld_cg_f(const float* p) {
    float v; asm volatile("ld.cg.f32 %0, [%1];" : "=f"(v) : "l"(p) : "memory");
    return v;
}
__device__ __forceinline__ void st_cg_u32(unsigned* p, unsigned v) {
    asm volatile("st.cg.u32 [%0], %1;" :: "l"(p), "r"(v) : "memory");
}
__device__ __forceinline__ unsigned atom_add_acqrel(unsigned* p, unsigned v) {
    unsigned old;
    asm volatile("atom.acq_rel.gpu.add.u32 %0, [%1], %2;"
                 : "=r"(old) : "l"(p), "r"(v) : "memory");
    return old;
}
__device__ __forceinline__ unsigned atom_add_release(unsigned* p, unsigned v) {
    unsigned old;
    asm volatile("atom.release.gpu.add.u32 %0, [%1], %2;"
                 : "=r"(old) : "l"(p), "r"(v) : "memory");
    return old;
}
__device__ __forceinline__ unsigned ld_acquire(const unsigned* p) {
    unsigned v;
    asm volatile("ld.acquire.gpu.u32 %0, [%1];" : "=r"(v) : "l"(p) : "memory");
    return v;
}
__device__ __forceinline__ float ldcg_gmem(const float* p) {
    float v; asm("ld.global.cg.f32 %0, [%1];" : "=f"(v) : "l"(p));
    return v;
}

// upper-triangle index into M (i<=j): i*10 - i(i+1)/2 + j
__device__ __forceinline__ float Mget(const float* sM, int a, int b) {
    int i = (a < b) ? a : b;
    int j = (a < b) ? b : a;
    return sM[i * 10 - (i * (i + 1)) / 2 + j];
}

__global__ __launch_bounds__(THREADS, 3)
void jac_kernel(const float* __restrict__ data,
                const float* __restrict__ W,
                float* __restrict__ out) {
    __shared__ u64   sW2[5 * DQ];      // W quarter, j-packed: sW2[jp*DQ + d]
    __shared__ float sM55[55];
    __shared__ float sRed[4];
    __shared__ bool  sFin, sLast;

    const int b    = blockIdx.x;
    const int q    = b & 3;
    const int set  = b >> 2;
    const int tid  = threadIdx.x;
    const int w    = tid >> 5;
    const int lane = tid & 31;

    // ---- stage this quarter of W into smem, j-packed ----
    #pragma unroll
    for (int c = 0; c < (5 * DQ) / THREADS; c++) {
        int idx = c * THREADS + tid;          // 3840 pairs
        int d  = idx / 5;
        int jp = idx - d * 5;
        const float2 t = *reinterpret_cast<const float2*>(
            W + (size_t)(q * DQ + d) * C_DIM + 2 * jp);
        sW2[jp * DQ + d] = pk2(t.x, t.y);
    }

    // ---- blocks 0..54: warp 0 computes one upper-tri M entry (full-D dot) ----
    if (b < 55 && w == 0) {
        int i = 0, rem = b;
        while (rem >= C_DIM - i) { rem -= C_DIM - i; i++; }
        const int j = i + rem;
        float s = 0.f;
        #pragma unroll 8
        for (int d = lane; d < D_DIM; d += 32)
            s = fmaf(W[(size_t)d * C_DIM + i], W[(size_t)d * C_DIM + j], s);
        #pragma unroll
        for (int off = 16; off; off >>= 1)
            s += __shfl_xor_sync(0xffffffffu, s, off);
        if (lane == 0) {
            st_cg_f(&g_M55[b], s);
            atom_add_release(&g_Mdone, 1u);
        }
    }
    __syncthreads();

    // ---- mainloop: warp covers 8 rows x this D-quarter ----
    const int r0 = set * SETROWS + w * RW;
    const float* xrow = data + (size_t)r0 * D_DIM + q * DQ;

    u64 acc[RW][5];
    #pragma unroll
    for (int r = 0; r < RW; r++)
        #pragma unroll
        for (int jp = 0; jp < 5; jp++) acc[r][jp] = 0ULL;

    #pragma unroll
    for (int it = 0; it < NIT; it++) {
        #pragma unroll
        for (int k = 0; k < 4; k++) {
            const int d = it * 128 + k * 32 + lane;
            float xv[RW];
            #pragma unroll
            for (int r = 0; r < RW; r++)
                xv[r] = ldcg_gmem(xrow + (size_t)r * D_DIM + d);
            u64 wv[5];
            #pragma unroll
            for (int jp = 0; jp < 5; jp++)
                wv[jp] = sW2[jp * DQ + d];
            #pragma unroll
            for (int r = 0; r < RW; r++) {
                const u64 xx = pk2(xv[r], xv[r]);
                #pragma unroll
                for (int jp = 0; jp < 5; jp++)
                    acc[r][jp] = ffma2(xx, wv[jp], acc[r][jp]);
            }
        }
    }

    // ---- butterfly reduce over lanes (packed), then store row partials ----
    #pragma unroll
    for (int r = 0; r < RW; r++)
        #pragma unroll
        for (int jp = 0; jp < 5; jp++) {
            u64 v = acc[r][jp];
            v = add2(v, shfl64(v, 16));
            v = add2(v, shfl64(v, 8));
            v = add2(v, shfl64(v, 4));
            v = add2(v, shfl64(v, 2));
            v = add2(v, shfl64(v, 1));
            acc[r][jp] = v;
        }
    #pragma unroll
    for (int r = 0; r < RW; r++) {
        if (lane == r) {
            u64* dst = g_zpart + ((size_t)(r0 + r) * QN + q) * 5;
            #pragma unroll
            for (int jp = 0; jp < 5; jp++) st_cg_u64(&dst[jp], acc[r][jp]);
        }
    }

    __syncthreads();
    if (tid == 0) sFin = (atom_add_acqrel(&g_setcnt[set], 1u) == QN - 1);
    __syncthreads();
    if (!sFin) return;

    // =====================================================================
    // Finisher block for this 32-row set: epilogue for rows set*32..+31
    // =====================================================================
    if (tid == 0) {                              // M is long since ready
        unsigned v = ld_acquire(&g_Mdone);
        while (v < 55) { __nanosleep(32); v = ld_acquire(&g_Mdone); }
        st_cg_u32(&g_setcnt[set], 0u);           // reset for next replay
    }
    __syncthreads();
    if (tid < 55) sM55[tid] = ld_cg_f(&g_M55[tid]);
    __syncthreads();

    float reg = 0.f;
    if (tid < SETROWS) {
        const int row = set * SETROWS + tid;
        const u64* src = g_zpart + (size_t)row * QN * 5;
        float z[C_DIM];
        #pragma unroll
        for (int jp = 0; jp < 5; jp++) {
            float a0, a1, b0, b1, c0, c1, d0, d1;
            unpk(ld_cg_u64(src + 0 * 5 + jp), a0, a1);
            unpk(ld_cg_u64(src + 1 * 5 + jp), b0, b1);
            unpk(ld_cg_u64(src + 2 * 5 + jp), c0, c1);
            unpk(ld_cg_u64(src + 3 * 5 + jp), d0, d1);
            z[2 * jp]     = (a0 + b0) + (c0 + d0);   // fixed order
            z[2 * jp + 1] = (a1 + b1) + (c1 + d1);
        }

        const float ALPHA = 1.0f - (float)C_DIM * NUM_STAB;
        float zmax = z[0];
        #pragma unroll
        for (int j = 1; j < C_DIM; j++) zmax = fmaxf(zmax, z[j]);

        float e[C_DIM], S = 0.f;
        #pragma unroll
        for (int j = 0; j < C_DIM; j++) { e[j] = expf(z[j] - zmax); S += e[j]; }
        const float invS = 1.f / S;

        float sig[C_DIM], p[C_DIM], s[C_DIM];
        float ssum = 0.f, psum_m = 0.f;
        #pragma unroll
        for (int j = 0; j < C_DIM; j++) {
            sig[j] = e[j] * invS;
            p[j]   = fmaf(ALPHA, sig[j], NUM_STAB);
            s[j]   = sqrtf(p[j]);
            ssum  += s[j];
            if (j < C_DIM - 1) psum_m += p[j];
        }
        const float sL = s[C_DIM - 1];
        const float t  = 1.f / (1.f - sL);

        float arg = ssum * 0.31622776601683794f;     // 1/sqrt(10)
        arg = fminf(1.f, fmaxf(-1.f, arg));
        const float delta = 2.f * acosf(arg);
        const float rho   = (2.f * (1.f - sL) - psum_m) * t;

        float v[C_DIM], qq = 0.f;
        #pragma unroll
        for (int k = 0; k < C_DIM; k++) {
            float a = 0.f;
            #pragma unroll
            for (int j = 0; j < C_DIM; j++)
                a = fmaf(Mget(sM55, k, j), sig[j], a);
            v[k] = a;
            qq = fmaf(sig[k], a, qq);
        }

        const float gL = ALPHA * sig[C_DIM - 1] / sL;
        float fro = 0.f;
        #pragma unroll
        for (int i = 0; i < C_DIM - 1; i++) {
            float a  = t * ALPHA * sig[i] / s[i];
            float bb = s[i] * t * t * gL;
            float c  = a + bb;
            fro += a * a * Mget(sM55, i, i)
                 + bb * bb * Mget(sM55, 9, 9)
                 + c * c * qq
                 + 2.f * a * bb * Mget(sM55, i, 9)
                 - 2.f * c * (a * v[i] + bb * v[C_DIM - 1]);
        }
        const float jac_norm = sqrtf(fmaxf(fro, 0.f));
        const float xv = jac_norm - delta / (rho * EPS_REG);
        reg = (xv > 0.f) ? xv : (expf(xv) - 1.f);
    }

    // set partial = sum of 32 rows (all in warp 0)
    if (w == 0) {
        #pragma unroll
        for (int off = 16; off; off >>= 1)
            reg += __shfl_xor_sync(0xffffffffu, reg, off);
        if (lane == 0) {
            st_cg_f(&g_partials[set], reg);
            sLast = (atom_add_acqrel(&g_count, 1u) == NSETS - 1);
        }
    }
    __syncthreads();

    // overall last finisher: fixed-order sum of 128 set partials
    if (sLast) {
        float vv = ld_cg_f(&g_partials[tid]);        // THREADS == NSETS == 128
        #pragma unroll
        for (int off = 16; off; off >>= 1)
            vv += __shfl_xor_sync(0xffffffffu, vv, off);
        if (lane == 0) sRed[w] = vv;
        __syncthreads();
        if (tid == 0) {
            float ssum = (sRed[0] + sRed[1]) + (sRed[2] + sRed[3]);
            out[0] = ssum * (1.0f / (float)B_DIM);
            st_cg_u32(&g_count, 0u);
            st_cg_u32(&g_Mdone, 0u);
        }
    }
}

extern "C" void kernel_launch(void* const* d_in, const int* in_sizes, int n_in,
                              void* d_out, int out_size) {
    const float* data = (const float*)d_in[0];   // [4096, 3072] f32
    const float* W    = (const float*)d_in[1];   // [3072, 10]   f32
    float* out        = (float*)d_out;           // scalar f32

    jac_kernel<<<NBLOCKS, THREADS>>>(data, W, out);
}

// round 10
// speedup vs baseline: 1.5727x; 1.4196x over previous
#include <cuda_runtime.h>
#include <math.h>

typedef unsigned long long u64;

#define D_DIM 3072
#define C_DIM 10
#define B_DIM 4096
#define BLOCKS 148
#define WARPS 7
#define THREADS 224
#define NT 24                 // 3072 / 128 tiles
#define NPAIR 15360           // 3072 * 5 packed W pairs

#define EPS_REG 0.1f
#define NUM_STAB 1e-6f

__device__ float g_M55[55];
__device__ float g_partials[BLOCKS];
__device__ unsigned g_Mdone = 0;
__device__ unsigned g_count = 0;

// ---- packed fp32x2 helpers ----
__device__ __forceinline__ u64 ffma2(u64 a, u64 b, u64 c) {
    u64 d; asm("fma.rn.f32x2 %0, %1, %2, %3;" : "=l"(d) : "l"(a), "l"(b), "l"(c));
    return d;
}
__device__ __forceinline__ u64 add2(u64 a, u64 b) {
    u64 d; asm("add.rn.f32x2 %0, %1, %2;" : "=l"(d) : "l"(a), "l"(b));
    return d;
}
__device__ __forceinline__ u64 pk2(float a, float b) {
    u64 r; asm("mov.b64 %0, {%1, %2};" : "=l"(r) : "f"(a), "f"(b));
    return r;
}
__device__ __forceinline__ void unpk(u64 v, float& lo, float& hi) {
    asm("mov.b64 {%0, %1}, %2;" : "=f"(lo), "=f"(hi) : "l"(v));
}
__device__ __forceinline__ u64 shfl64(u64 v, int m) {
    unsigned lo, hi;
    asm("mov.b64 {%0, %1}, %2;" : "=r"(lo), "=r"(hi) : "l"(v));
    lo = __shfl_xor_sync(0xffffffffu, lo, m);
    hi = __shfl_xor_sync(0xffffffffu, hi, m);
    u64 r; asm("mov.b64 %0, {%1, %2};" : "=l"(r) : "r"(lo), "r"(hi));
    return r;
}

// ---- L2-scoped helpers (no threadfence -> no L1 flush) ----
__device__ __forceinline__ void st_cg_f(float* p, float v) {
    asm volatile("st.cg.f32 [%0], %1;" :: "l"(p), "f"(v) : "memory");
}
__device__ __forceinline__ float ld_cg_f(const float* p) {
    float v; asm volatile("ld.cg.f32 %0, [%1];" : "=f"(v) : "l"(p) : "memory");
    return v;
}
__device__ __forceinline__ void st_cg_u32(unsigned* p, unsigned v) {
    asm volatile("st.cg.u32 [%0], %1;" :: "l"(p), "r"(v) : "memory");
}
__device__ __forceinline__ unsigned atom_add_acqrel(unsigned* p, unsigned v) {
    unsigned old;
    asm volatile("atom.acq_rel.gpu.add.u32 %0, [%1], %2;"
                 : "=r"(old) : "l"(p), "r"(v) : "memory");
    return old;
}
__device__ __forceinline__ unsigned atom_add_release(unsigned* p, unsigned v) {
    unsigned old;
    asm volatile("atom.release.gpu.add.u32 %0, [%1], %2;"
                 : "=r"(old) : "l"(p), "r"(v) : "memory");
    return old;
}
__device__ __forceinline__ unsigned ld_acquire(const unsigned* p) {
    unsigned v;
    asm volatile("ld.acquire.gpu.u32 %0, [%1];" : "=r"(v) : "l"(p) : "memory");
    return v;
}

// upper-triangle index into M (i<=j): i*10 - i(i+1)/2 + j
__device__ __forceinline__ float Mget(const float* sM, int a, int b) {
    int i = (a < b) ? a : b;
    int j = (a < b) ? b : a;
    return sM[i * 10 - (i * (i + 1)) / 2 + j];
}

extern __shared__ unsigned char smem_raw[];

__global__ __launch_bounds__(THREADS, 1)
void jac_kernel(const float* __restrict__ data,
                const float* __restrict__ W,
                float* __restrict__ out) {
    u64*   sW2  = (u64*)smem_raw;                 // [5][3072] packed W pairs
    float* sM55 = (float*)(sW2 + NPAIR);          // 55
    float* sWs  = sM55 + 56;                      // 7 warp partials
    __shared__ bool sLast;

    const int tid  = threadIdx.x;
    const int w    = tid >> 5;
    const int lane = tid & 31;
    const int b    = blockIdx.x;
    const int nrb     = (b < 100) ? 28 : 27;
    const int rowbase = (b < 100) ? 28 * b : 2800 + 27 * (b - 100);

    // ---- stage W into smem, j-packed (coalesced float2 reads) ----
    for (int i = tid; i < NPAIR; i += THREADS) {
        int d  = i / 5;
        int jp = i - d * 5;
        float2 t = *reinterpret_cast<const float2*>(W + (size_t)d * C_DIM + 2 * jp);
        sW2[(size_t)jp * D_DIM + d] = pk2(t.x, t.y);
    }

    // ---- blocks 0..54: warp 0 computes one upper-tri M entry, publishes ----
    if (b < 55 && w == 0) {
        int i = 0, rem = b;
        while (rem >= C_DIM - i) { rem -= C_DIM - i; i++; }
        const int j = i + rem;
        float s = 0.f;
        #pragma unroll 8
        for (int d = lane; d < D_DIM; d += 32)
            s = fmaf(W[(size_t)d * C_DIM + i], W[(size_t)d * C_DIM + j], s);
        #pragma unroll
        for (int off = 16; off; off >>= 1)
            s += __shfl_xor_sync(0xffffffffu, s, off);
        if (lane == 0) {
            st_cg_f(&g_M55[b], s);
            atom_add_release(&g_Mdone, 1u);
        }
    }
    __syncthreads();

    // ---- row assignment: warp w covers 4 rows (last warp may clamp) ----
    const int r0 = rowbase + w * 4;
    const int nr = min(4, nrb - w * 4);
    const float* xp[4];
    #pragma unroll
    for (int r = 0; r < 4; r++) {
        int rr = r0 + ((r < nr) ? r : nr - 1);
        xp[r] = data + (size_t)rr * D_DIM + lane * 4;
    }

    // ---- mainloop: 24 tiles of 128 d, 3-stage x prefetch ----
    u64 acc[4][5];
    #pragma unroll
    for (int r = 0; r < 4; r++)
        #pragma unroll
        for (int jp = 0; jp < 5; jp++) acc[r][jp] = 0ULL;

    float4 xb[3][4];
    #pragma unroll
    for (int s = 0; s < 2; s++)
        #pragma unroll
        for (int r = 0; r < 4; r++)
            xb[s][r] = *reinterpret_cast<const float4*>(xp[r] + s * 128);

    const u64* wlane = sW2 + lane * 4;

    #pragma unroll 6
    for (int t = 0; t < NT; t++) {
        const int cur = t % 3;
        if (t + 2 < NT) {
            const int nxt = (t + 2) % 3;
            #pragma unroll
            for (int r = 0; r < 4; r++)
                xb[nxt][r] = *reinterpret_cast<const float4*>(xp[r] + (t + 2) * 128);
        }
        const u64* wt = wlane + t * 128;
        // first 2 d of the lane's 4
        {
            u64 wv[5][2];
            #pragma unroll
            for (int jp = 0; jp < 5; jp++) {
                wv[jp][0] = wt[(size_t)jp * D_DIM + 0];
                wv[jp][1] = wt[(size_t)jp * D_DIM + 1];
            }
            #pragma unroll
            for (int r = 0; r < 4; r++) {
                const u64 x0 = pk2(xb[cur][r].x, xb[cur][r].x);
                const u64 x1 = pk2(xb[cur][r].y, xb[cur][r].y);
                #pragma unroll
                for (int jp = 0; jp < 5; jp++)
                    acc[r][jp] = ffma2(x1, wv[jp][1], ffma2(x0, wv[jp][0], acc[r][jp]));
            }
        }
        // last 2 d
        {
            u64 wv[5][2];
            #pragma unroll
            for (int jp = 0; jp < 5; jp++) {
                wv[jp][0] = wt[(size_t)jp * D_DIM + 2];
                wv[jp][1] = wt[(size_t)jp * D_DIM + 3];
            }
            #pragma unroll
            for (int r = 0; r < 4; r++) {
                const u64 x2 = pk2(xb[cur][r].z, xb[cur][r].z);
                const u64 x3 = pk2(xb[cur][r].w, xb[cur][r].w);
                #pragma unroll
                for (int jp = 0; jp < 5; jp++)
                    acc[r][jp] = ffma2(x3, wv[jp][1], ffma2(x2, wv[jp][0], acc[r][jp]));
            }
        }
    }

    // ---- packed butterfly reduce: all lanes end with full sums ----
    #pragma unroll
    for (int r = 0; r < 4; r++)
        #pragma unroll
        for (int jp = 0; jp < 5; jp++) {
            u64 v = acc[r][jp];
            v = add2(v, shfl64(v, 16));
            v = add2(v, shfl64(v, 8));
            v = add2(v, shfl64(v, 4));
            v = add2(v, shfl64(v, 2));
            v = add2(v, shfl64(v, 1));
            acc[r][jp] = v;
        }

    // ---- wait for M, load to smem ----
    __syncthreads();
    if (tid == 0) {
        unsigned v = ld_acquire(&g_Mdone);
        while (v < 55) { __nanosleep(32); v = ld_acquire(&g_Mdone); }
    }
    __syncthreads();
    if (tid < 55) sM55[tid] = ld_cg_f(&g_M55[tid]);
    __syncthreads();

    // ---- analytic epilogue: lane r (< nr) handles row r0+r ----
    float reg = 0.f;
    if (lane < nr) {
        const float ALPHA = 1.0f - (float)C_DIM * NUM_STAB;
        float z[C_DIM];
        #pragma unroll
        for (int jp = 0; jp < 5; jp++) {
            u64 v = acc[0][jp];
            v = (lane == 1) ? acc[1][jp] : v;
            v = (lane == 2) ? acc[2][jp] : v;
            v = (lane == 3) ? acc[3][jp] : v;
            unpk(v, z[2 * jp], z[2 * jp + 1]);
        }

        float zmax = z[0];
        #pragma unroll
        for (int j = 1; j < C_DIM; j++) zmax = fmaxf(zmax, z[j]);

        float e[C_DIM], S = 0.f;
        #pragma unroll
        for (int j = 0; j < C_DIM; j++) { e[j] = expf(z[j] - zmax); S += e[j]; }
        const float invS = 1.f / S;

        float sig[C_DIM], p[C_DIM], s[C_DIM];
        float ssum = 0.f, psum_m = 0.f;
        #pragma unroll
        for (int j = 0; j < C_DIM; j++) {
            sig[j] = e[j] * invS;
            p[j]   = fmaf(ALPHA, sig[j], NUM_STAB);
            s[j]   = sqrtf(p[j]);
            ssum  += s[j];
            if (j < C_DIM - 1) psum_m += p[j];
        }
        const float sL = s[C_DIM - 1];
        const float t  = 1.f / (1.f - sL);

        float arg = ssum * 0.31622776601683794f;       // 1/sqrt(10)
        arg = fminf(1.f, fmaxf(-1.f, arg));
        const float delta = 2.f * acosf(arg);
        const float rho   = (2.f * (1.f - sL) - psum_m) * t;

        float v[C_DIM], qq = 0.f;
        #pragma unroll
        for (int k = 0; k < C_DIM; k++) {
            float a = 0.f;
            #pragma unroll
            for (int j = 0; j < C_DIM; j++)
                a = fmaf(Mget(sM55, k, j), sig[j], a);
            v[k] = a;
            qq = fmaf(sig[k], a, qq);
        }

        const float gL = ALPHA * sig[C_DIM - 1] / sL;
        float fro = 0.f;
        #pragma unroll
        for (int i = 0; i < C_DIM - 1; i++) {
            float a  = t * ALPHA * sig[i] / s[i];
            float bb = s[i] * t * t * gL;
            float c  = a + bb;
            fro += a * a * Mget(sM55, i, i)
                 + bb * bb * Mget(sM55, 9, 9)
                 + c * c * qq
                 + 2.f * a * bb * Mget(sM55, i, 9)
                 - 2.f * c * (a * v[i] + bb * v[C_DIM - 1]);
        }
        const float jac_norm = sqrtf(fmaxf(fro, 0.f));
        const float xv = jac_norm - delta / (rho * EPS_REG);
        reg = (xv > 0.f) ? xv : (expf(xv) - 1.f);
    }

    // ---- deterministic block reduction ----
    #pragma unroll
    for (int off = 16; off; off >>= 1)
        reg += __shfl_xor_sync(0xffffffffu, reg, off);
    if (lane == 0) sWs[w] = reg;
    __syncthreads();
    if (tid == 0) {
        float ssum = 0.f;
        #pragma unroll
        for (int k = 0; k < WARPS; k++) ssum += sWs[k];
        st_cg_f(&g_partials[b], ssum);
        sLast = (atom_add_acqrel(&g_count, 1u) == BLOCKS - 1);
    }
    __syncthreads();

    // ---- last block: fixed-order final reduction over 148 partials ----
    if (sLast) {
        float v = (tid < BLOCKS) ? ld_cg_f(&g_partials[tid]) : 0.f;
        #pragma unroll
        for (int off = 16; off; off >>= 1)
            v += __shfl_xor_sync(0xffffffffu, v, off);
        if (lane == 0) sWs[w] = v;
        __syncthreads();
        if (tid == 0) {
            float ssum = 0.f;
            #pragma unroll
            for (int k = 0; k < WARPS; k++) ssum += sWs[k];
            out[0] = ssum * (1.0f / (float)B_DIM);
            st_cg_u32(&g_count, 0u);
            st_cg_u32(&g_Mdone, 0u);
        }
    }
}

extern "C" void kernel_launch(void* const* d_in, const int* in_sizes, int n_in,
                              void* d_out, int out_size) {
    const float* data = (const float*)d_in[0];   // [4096, 3072] f32
    const float* W    = (const float*)d_in[1];   // [3072, 10]   f32
    float* out        = (float*)d_out;           // scalar f32

    const int smemBytes = NPAIR * 8 + 64 * 4;    // ~123.1 KB
    cudaFuncSetAttribute(jac_kernel, cudaFuncAttributeMaxDynamicSharedMemorySize,
                         smemBytes);
    jac_kernel<<<BLOCKS, THREADS, smemBytes>>>(data, W, out);
}